// round 15
// baseline (speedup 1.0000x reference)
// GraphConvolution_49177375539507 — fused tf32 mma.sync kernel for GB300 (sm_103a)
// R13: reassociated form  out[b] = sum_e (adj_be @ node_b) @ W_e
//                                  + rowsum(adj_be) x b_e + node_b @ W_add + b_add
// node is the SHARED B operand (staged once, pair-interleaved smem) -> the adj
// streaming loop runs as one flat 32-chunk per-warp cp.async pipeline with no
// per-edge phase breaks. P_e = adj@node accumulates in registers; at each edge
// boundary a small GEMM P_e @ W_e folds into the output accumulators, with
// A-fragments extracted from P C-fragments via intra-quad shuffles (no smem
// round trip). Bias term uses rowsums accumulated on the idle FMA pipe.
// W is ping-pong double-buffered (2 cheap barriers per edge).
//
// One CTA per b (grid 512), 256 threads (8 warps), each warp owns 32 output rows.
// adj fed as raw fp32 bits to tf32 mma (HW truncation); node/W/P rounded with
// cvt.rna.tf32.

#include <cuda_runtime.h>
#include <cstdint>

#define N_SZ 256
#define F_SZ 64
#define E_SZ 4
#define NTHREADS 256
#define MR 32                              // output rows per warp
#define ADJ_STRIDE 36                      // floats per row in a warp's adj chunk
#define WBUF_FLOATS (MR * ADJ_STRIDE)      // 1152 floats per slot per warp
#define NSLOT 3

// smem layout (floats)
#define SH_NODE 0                          // 256x64 = 16384 (pair-interleaved B tile)
#define SH_W    16384                      // 2 x 4096 (ping-pong, XOR-swizzled)
#define SH_BA   24576                      // 64  (b_add)
#define SH_BE   24640                      // 256 (b_edge, all 4)
#define SH_RING 24896                      // 8 warps * 3 slots * 1152 = 27648
#define SMEM_FLOATS 52544
#define SMEM_BYTES (SMEM_FLOATS * 4)       // 210176 B

__device__ __forceinline__ int swz(int r, int c) { return c ^ ((r & 3) << 3); }

// pair-interleaved address: (k,n) and (k+4,n) adjacent words (k = node row, n = col)
__device__ __forceinline__ int paddr(int k, int n) {
    return ((k >> 3) << 9) + (n << 3) + ((k & 3) << 1) + ((k >> 2) & 1);
}

__device__ __forceinline__ uint32_t f2tf(float f) {
    uint32_t r;
    asm("cvt.rna.tf32.f32 %0, %1;" : "=r"(r) : "f"(f));
    return r;
}

__device__ __forceinline__ void mma_tf32(float (&d)[4], const uint32_t (&a)[4],
                                         const uint32_t (&b)[2]) {
    asm volatile(
        "mma.sync.aligned.m16n8k8.row.col.f32.tf32.tf32.f32 "
        "{%0,%1,%2,%3}, {%4,%5,%6,%7}, {%8,%9}, {%0,%1,%2,%3};\n"
        : "+f"(d[0]), "+f"(d[1]), "+f"(d[2]), "+f"(d[3])
        : "r"(a[0]), "r"(a[1]), "r"(a[2]), "r"(a[3]), "r"(b[0]), "r"(b[1]));
}

__device__ __forceinline__ void cp_async16(void* smem_ptr, const void* gmem_ptr) {
    unsigned sa = (unsigned)__cvta_generic_to_shared(smem_ptr);
    asm volatile("cp.async.cg.shared.global [%0], [%1], 16;\n" :: "r"(sa), "l"(gmem_ptr));
}
__device__ __forceinline__ void cp_commit() { asm volatile("cp.async.commit_group;\n"); }
template <int N> __device__ __forceinline__ void cp_wait() {
    asm volatile("cp.async.wait_group %0;\n" :: "n"(N));
}

// Per-warp adj chunk load: 32 rows x 32 cols of adj[b, e], chunk kc.
__device__ __forceinline__ void issue_adj_warp(float* __restrict__ wbuf,
                                               const float* __restrict__ adj_w,
                                               int kc, int lane) {
    const int row = lane >> 3;                 // 0..3
    const int cf  = (lane & 7) << 2;
    const float* src = adj_w + row * 256 + kc * 32 + cf;
    float* dst = wbuf + row * ADJ_STRIDE + cf;
#pragma unroll
    for (int ii = 0; ii < 8; ++ii)
        cp_async16(dst + ii * 4 * ADJ_STRIDE, src + ii * 4 * 256);
}

// stage a 64x64 W (tf32, XOR-swizzled, k-major) into one ping-pong buffer
__device__ __forceinline__ void stage_W(float* __restrict__ shw,
                                        const float* __restrict__ W, int tid) {
    const float4* src = (const float4*)W;
#pragma unroll
    for (int i = 0; i < 4; ++i) {
        const int idx = tid + i * NTHREADS;       // 1024 float4
        const int r = idx >> 4;
        const int c = (idx & 15) << 2;
        float4 v = src[idx];
        uint32_t* dst = (uint32_t*)&shw[r * 64 + swz(r, c)];
        dst[0] = f2tf(v.x); dst[1] = f2tf(v.y); dst[2] = f2tf(v.z); dst[3] = f2tf(v.w);
    }
}

__global__ void __launch_bounds__(NTHREADS, 1)
graphconv_tf32_kernel(const float* __restrict__ node,
                      const float* __restrict__ adj,
                      const float* __restrict__ W_edge,
                      const float* __restrict__ b_edge,
                      const float* __restrict__ W_add,
                      const float* __restrict__ b_add,
                      float* __restrict__ out) {
    extern __shared__ float smem[];
    float* sh_node = smem + SH_NODE;
    float* sh_w    = smem + SH_W;
    float* sh_ba   = smem + SH_BA;
    float* sh_be   = smem + SH_BE;

    const int tid  = threadIdx.x;
    const int w    = tid >> 5;
    const int lane = tid & 31;
    const int qr   = lane >> 2;
    const int qc   = lane & 3;
    const int mrow = w * MR;
    const int b    = blockIdx.x;

    float* wbuf = smem + SH_RING + w * NSLOT * WBUF_FLOATS;
    const float* adj_b = adj + (((size_t)b * E_SZ) << 16);
    const float* adj_w0 = adj_b + mrow * 256;

    // ---- prologue: kick off flat chunks g=0,1,2 (edge 0, kc 0..2) ----
    issue_adj_warp(wbuf,                   adj_w0, 0, lane); cp_commit();
    issue_adj_warp(wbuf + 1 * WBUF_FLOATS, adj_w0, 1, lane); cp_commit();
    issue_adj_warp(wbuf + 2 * WBUF_FLOATS, adj_w0, 2, lane); cp_commit();

    // ---- stage node[b] as shared B tile (tf32, pair-interleaved) ----
    {
        const float4* src = (const float4*)(node + (size_t)b * N_SZ * F_SZ);
#pragma unroll
        for (int i = 0; i < 16; ++i) {
            const int q = tid + i * NTHREADS;   // 4096 float4
            const int r = q >> 4;
            const int c = (q & 15) << 2;
            float4 v = src[q];
            sh_node[paddr(r, c + 0)] = __uint_as_float(f2tf(v.x));
            sh_node[paddr(r, c + 1)] = __uint_as_float(f2tf(v.y));
            sh_node[paddr(r, c + 2)] = __uint_as_float(f2tf(v.z));
            sh_node[paddr(r, c + 3)] = __uint_as_float(f2tf(v.w));
        }
    }
    stage_W(sh_w, W_add, tid);                 // buf0 = W_add
    if (tid < 64) sh_ba[tid] = b_add[tid];
    sh_be[tid] = b_edge[tid];                  // all 4 edge biases (256 floats)
    __syncthreads();

    // ---- residual: oacc = b_add + node @ W_add (A-frags from node B tile) ----
    float oacc[2][8][4];
#pragma unroll
    for (int nt = 0; nt < 8; ++nt) {
        const float v0 = sh_ba[8 * nt + 2 * qc];
        const float v1 = sh_ba[8 * nt + 2 * qc + 1];
#pragma unroll
        for (int j = 0; j < 2; ++j) {
            oacc[j][nt][0] = v0; oacc[j][nt][1] = v1;
            oacc[j][nt][2] = v0; oacc[j][nt][3] = v1;
        }
    }
#pragma unroll
    for (int s = 0; s < 8; ++s) {
        uint32_t bf[8][2];
        const int kr0 = 8 * s + qc;
#pragma unroll
        for (int nt = 0; nt < 8; ++nt) {
            const int cc = (8 * nt + qr) ^ (qc << 3);
            bf[nt][0] = *(const uint32_t*)&sh_w[kr0 * 64 + cc];
            bf[nt][1] = *(const uint32_t*)&sh_w[(kr0 + 4) * 64 + cc];
        }
#pragma unroll
        for (int j = 0; j < 2; ++j) {
            const int r0 = mrow + 16 * j + qr;
            uint32_t af[4];
            af[0] = *(const uint32_t*)&sh_node[paddr(r0,     8 * s + qc)];
            af[1] = *(const uint32_t*)&sh_node[paddr(r0 + 8, 8 * s + qc)];
            af[2] = *(const uint32_t*)&sh_node[paddr(r0,     8 * s + qc + 4)];
            af[3] = *(const uint32_t*)&sh_node[paddr(r0 + 8, 8 * s + qc + 4)];
#pragma unroll
            for (int nt = 0; nt < 8; ++nt) mma_tf32(oacc[j][nt], af, bf[nt]);
        }
    }

    stage_W(sh_w + 4096, W_edge, tid);         // buf1 = W_0
    __syncthreads();

    // ---- flat streaming loop: 32 chunks (4 edges x 8), no phase breaks ----
    float pacc[2][8][4];
#pragma unroll
    for (int j = 0; j < 2; ++j)
#pragma unroll
        for (int nt = 0; nt < 8; ++nt)
#pragma unroll
            for (int i = 0; i < 4; ++i) pacc[j][nt][i] = 0.0f;
    float rs[2][2] = {{0.0f, 0.0f}, {0.0f, 0.0f}};

    int slot = 0;                              // g % 3
#pragma unroll 1
    for (int g = 0; g < 32; ++g) {
        const int e  = g >> 3;
        const int kc = g & 7;

        if (g <= 29)      cp_wait<2>();
        else if (g == 30) cp_wait<1>();
        else              cp_wait<0>();
        __syncwarp();

        const float* abuf = wbuf + slot * WBUF_FLOATS;
#pragma unroll
        for (int s = 0; s < 4; ++s) {
            const float* gbase = sh_node + ((4 * kc + s) << 9);
            uint32_t bf[8][2];
#pragma unroll
            for (int nt = 0; nt < 8; ++nt) {
                uint2 pr = *(const uint2*)&gbase[((8 * nt + qr) << 3) + (qc << 1)];
                bf[nt][0] = pr.x; bf[nt][1] = pr.y;
            }
            const int cl = 8 * s + qc;
#pragma unroll
            for (int j = 0; j < 2; ++j) {
                const int lr = 16 * j + qr;
                uint32_t af[4];
                af[0] = *(const uint32_t*)&abuf[lr * ADJ_STRIDE + cl];
                af[1] = *(const uint32_t*)&abuf[(lr + 8) * ADJ_STRIDE + cl];
                af[2] = *(const uint32_t*)&abuf[lr * ADJ_STRIDE + cl + 4];
                af[3] = *(const uint32_t*)&abuf[(lr + 8) * ADJ_STRIDE + cl + 4];
                rs[j][0] += __uint_as_float(af[0]) + __uint_as_float(af[2]);
                rs[j][1] += __uint_as_float(af[1]) + __uint_as_float(af[3]);
#pragma unroll
                for (int nt = 0; nt < 8; ++nt) mma_tf32(pacc[j][nt], af, bf[nt]);
            }
        }
        __syncwarp();

        // refill just-consumed slot with flat chunk g+3 (crosses edges seamlessly)
        if (g + 3 < 32) {
            const int gn = g + 3;
            issue_adj_warp(wbuf + slot * WBUF_FLOATS,
                           adj_b + (((size_t)(gn >> 3)) << 16) + mrow * 256,
                           gn & 7, lane);
            cp_commit();
        }
        slot = (slot == 2) ? 0 : slot + 1;

        if (kc == 7) {
            // ---- edge boundary: fold rowsum x b_e, then oacc += P_e @ W_e ----
            const float* be = sh_be + (e << 6);
            float rt[2][2];
#pragma unroll
            for (int j = 0; j < 2; ++j)
#pragma unroll
                for (int i = 0; i < 2; ++i) {
                    float v = rs[j][i];
                    v += __shfl_xor_sync(0xffffffffu, v, 1);
                    v += __shfl_xor_sync(0xffffffffu, v, 2);
                    rt[j][i] = v;
                    rs[j][i] = 0.0f;
                }
#pragma unroll
            for (int nt = 0; nt < 8; ++nt) {
                const float b0 = be[8 * nt + 2 * qc];
                const float b1 = be[8 * nt + 2 * qc + 1];
#pragma unroll
                for (int j = 0; j < 2; ++j) {
                    oacc[j][nt][0] += rt[j][0] * b0;
                    oacc[j][nt][1] += rt[j][0] * b1;
                    oacc[j][nt][2] += rt[j][1] * b0;
                    oacc[j][nt][3] += rt[j][1] * b1;
                }
            }
            // small GEMM: A-frags from pacc via intra-quad shuffles
            const float* shw = sh_w + (((e + 1) & 1) << 12);
            const int L1 = (lane & ~3) | (qc >> 1);
            const int L2 = L1 ^ 2;
            const bool odd = qc & 1;
#pragma unroll
            for (int s = 0; s < 8; ++s) {
                uint32_t bf[8][2];
                const int kr0 = 8 * s + qc;
#pragma unroll
                for (int nt = 0; nt < 8; ++nt) {
                    const int cc = (8 * nt + qr) ^ (qc << 3);
                    bf[nt][0] = *(const uint32_t*)&shw[kr0 * 64 + cc];
                    bf[nt][1] = *(const uint32_t*)&shw[(kr0 + 4) * 64 + cc];
                }
#pragma unroll
                for (int j = 0; j < 2; ++j) {
                    const float v00 = __shfl_sync(0xffffffffu, pacc[j][s][0], L1);
                    const float v01 = __shfl_sync(0xffffffffu, pacc[j][s][1], L1);
                    const float v10 = __shfl_sync(0xffffffffu, pacc[j][s][2], L1);
                    const float v11 = __shfl_sync(0xffffffffu, pacc[j][s][3], L1);
                    const float u00 = __shfl_sync(0xffffffffu, pacc[j][s][0], L2);
                    const float u01 = __shfl_sync(0xffffffffu, pacc[j][s][1], L2);
                    const float u10 = __shfl_sync(0xffffffffu, pacc[j][s][2], L2);
                    const float u11 = __shfl_sync(0xffffffffu, pacc[j][s][3], L2);
                    uint32_t a[4];
                    a[0] = f2tf(odd ? v01 : v00);
                    a[1] = f2tf(odd ? v11 : v10);
                    a[2] = f2tf(odd ? u01 : u00);
                    a[3] = f2tf(odd ? u11 : u10);
#pragma unroll
                    for (int nt = 0; nt < 8; ++nt) mma_tf32(oacc[j][nt], a, bf[nt]);
                }
            }
            // reset P accumulators for next edge
#pragma unroll
            for (int j = 0; j < 2; ++j)
#pragma unroll
                for (int nt = 0; nt < 8; ++nt)
#pragma unroll
                    for (int i = 0; i < 4; ++i) pacc[j][nt][i] = 0.0f;

            if (e < 3) {
                __syncthreads();   // all warps done with W_{e-1} buffer
                stage_W(sh_w + (((e /*+2*/) & 1) << 12), W_edge + (e + 1) * 4096, tid);
                __syncthreads();   // W_{e+1} visible before its small GEMM
            }
        }
    }

    // ---- epilogue: write out[b] ----
    float* ob = out + (size_t)b * N_SZ * F_SZ;
#pragma unroll
    for (int j = 0; j < 2; ++j) {
#pragma unroll
        for (int nt = 0; nt < 8; ++nt) {
            const int r0 = mrow + 16 * j + qr;
            const int c0 = 8 * nt + 2 * qc;
            *(float2*)&ob[r0 * 64 + c0]       = make_float2(oacc[j][nt][0], oacc[j][nt][1]);
            *(float2*)&ob[(r0 + 8) * 64 + c0] = make_float2(oacc[j][nt][2], oacc[j][nt][3]);
        }
    }
}

extern "C" void kernel_launch(void* const* d_in, const int* in_sizes, int n_in,
                              void* d_out, int out_size) {
    const float* node   = (const float*)d_in[0];
    const float* adj    = (const float*)d_in[1];
    const float* W_edge = (const float*)d_in[2];
    const float* b_edge = (const float*)d_in[3];
    const float* W_add  = (const float*)d_in[4];
    const float* b_add  = (const float*)d_in[5];
    float* out = (float*)d_out;

    cudaFuncSetAttribute(graphconv_tf32_kernel,
                         cudaFuncAttributeMaxDynamicSharedMemorySize, SMEM_BYTES);
    graphconv_tf32_kernel<<<512, NTHREADS, SMEM_BYTES>>>(node, adj, W_edge, b_edge,
                                                         W_add, b_add, out);
}

// round 16
// speedup vs baseline: 1.0002x; 1.0002x over previous
// GraphConvolution_49177375539507 — fused tf32 mma.sync kernel for GB300 (sm_103a)
// R15: reassociated form  out[b] = sum_e (adj_be @ node_b) @ W_e
//                                  + rowsum(adj_be) x b_e + node_b @ W_add + b_add
// (R13 algorithm) + restored 3-deep cp.async pipeline (R10 discipline):
//   - 4-slot per-warp ring, refill BEFORE compute, wait_group<3>
//     -> 3 chunks in flight during every compute step.
//   - single W buffer (no ping-pong); W_{e+1} staged at the edge boundary between
//     two block barriers, covered by the next edge's in-flight chunks.
// node is the SHARED B operand (staged once, pair-interleaved smem); the adj
// stream runs as one flat 32-chunk pipeline with no phase breaks. P_e = adj@node
// accumulates in registers; at each edge boundary P_e @ W_e folds into the output
// accumulators via intra-quad shuffles (no smem round trip). Bias term uses
// rowsums accumulated on the idle FMA pipe.
//
// One CTA per b (grid 512), 256 threads (8 warps), each warp owns 32 output rows.
// adj fed as raw fp32 bits to tf32 mma (HW truncation); node/W/P rounded with
// cvt.rna.tf32.

#include <cuda_runtime.h>
#include <cstdint>

#define N_SZ 256
#define F_SZ 64
#define E_SZ 4
#define NTHREADS 256
#define MR 32                              // output rows per warp
#define ADJ_STRIDE 36                      // floats per row in a warp's adj chunk
#define WBUF_FLOATS (MR * ADJ_STRIDE)      // 1152 floats per slot per warp
#define NSLOT 4

// smem layout (floats)
#define SH_NODE 0                          // 256x64 = 16384 (pair-interleaved B tile)
#define SH_W    16384                      // 4096 (single buffer, XOR-swizzled)
#define SH_BA   20480                      // 64  (b_add)
#define SH_BE   20544                      // 256 (b_edge, all 4)
#define SH_RING 20800                      // 8 warps * 4 slots * 1152 = 36864
#define SMEM_FLOATS 57664
#define SMEM_BYTES (SMEM_FLOATS * 4)       // 230656 B

__device__ __forceinline__ int swz(int r, int c) { return c ^ ((r & 3) << 3); }

// pair-interleaved address: (k,n) and (k+4,n) adjacent words (k = node row, n = col)
__device__ __forceinline__ int paddr(int k, int n) {
    return ((k >> 3) << 9) + (n << 3) + ((k & 3) << 1) + ((k >> 2) & 1);
}

__device__ __forceinline__ uint32_t f2tf(float f) {
    uint32_t r;
    asm("cvt.rna.tf32.f32 %0, %1;" : "=r"(r) : "f"(f));
    return r;
}

__device__ __forceinline__ void mma_tf32(float (&d)[4], const uint32_t (&a)[4],
                                         const uint32_t (&b)[2]) {
    asm volatile(
        "mma.sync.aligned.m16n8k8.row.col.f32.tf32.tf32.f32 "
        "{%0,%1,%2,%3}, {%4,%5,%6,%7}, {%8,%9}, {%0,%1,%2,%3};\n"
        : "+f"(d[0]), "+f"(d[1]), "+f"(d[2]), "+f"(d[3])
        : "r"(a[0]), "r"(a[1]), "r"(a[2]), "r"(a[3]), "r"(b[0]), "r"(b[1]));
}

__device__ __forceinline__ void cp_async16(void* smem_ptr, const void* gmem_ptr) {
    unsigned sa = (unsigned)__cvta_generic_to_shared(smem_ptr);
    asm volatile("cp.async.cg.shared.global [%0], [%1], 16;\n" :: "r"(sa), "l"(gmem_ptr));
}
__device__ __forceinline__ void cp_commit() { asm volatile("cp.async.commit_group;\n"); }
template <int N> __device__ __forceinline__ void cp_wait() {
    asm volatile("cp.async.wait_group %0;\n" :: "n"(N));
}

// Per-warp adj chunk load: 32 rows x 32 cols of adj[b, e], chunk kc.
__device__ __forceinline__ void issue_adj_warp(float* __restrict__ wbuf,
                                               const float* __restrict__ adj_w,
                                               int kc, int lane) {
    const int row = lane >> 3;                 // 0..3
    const int cf  = (lane & 7) << 2;
    const float* src = adj_w + row * 256 + kc * 32 + cf;
    float* dst = wbuf + row * ADJ_STRIDE + cf;
#pragma unroll
    for (int ii = 0; ii < 8; ++ii)
        cp_async16(dst + ii * 4 * ADJ_STRIDE, src + ii * 4 * 256);
}

// stage a 64x64 W (tf32, XOR-swizzled, k-major)
__device__ __forceinline__ void stage_W(float* __restrict__ shw,
                                        const float* __restrict__ W, int tid) {
    const float4* src = (const float4*)W;
#pragma unroll
    for (int i = 0; i < 4; ++i) {
        const int idx = tid + i * NTHREADS;       // 1024 float4
        const int r = idx >> 4;
        const int c = (idx & 15) << 2;
        float4 v = src[idx];
        uint32_t* dst = (uint32_t*)&shw[r * 64 + swz(r, c)];
        dst[0] = f2tf(v.x); dst[1] = f2tf(v.y); dst[2] = f2tf(v.z); dst[3] = f2tf(v.w);
    }
}

__global__ void __launch_bounds__(NTHREADS, 1)
graphconv_tf32_kernel(const float* __restrict__ node,
                      const float* __restrict__ adj,
                      const float* __restrict__ W_edge,
                      const float* __restrict__ b_edge,
                      const float* __restrict__ W_add,
                      const float* __restrict__ b_add,
                      float* __restrict__ out) {
    extern __shared__ float smem[];
    float* sh_node = smem + SH_NODE;
    float* sh_w    = smem + SH_W;
    float* sh_ba   = smem + SH_BA;
    float* sh_be   = smem + SH_BE;

    const int tid  = threadIdx.x;
    const int w    = tid >> 5;
    const int lane = tid & 31;
    const int qr   = lane >> 2;
    const int qc   = lane & 3;
    const int mrow = w * MR;
    const int b    = blockIdx.x;

    float* wbuf = smem + SH_RING + w * NSLOT * WBUF_FLOATS;
    const float* adj_b = adj + (((size_t)b * E_SZ) << 16);
    const float* adj_w0 = adj_b + mrow * 256;

    // ---- prologue: kick off flat chunks g=0,1,2 into slots 0,1,2 ----
    issue_adj_warp(wbuf,                   adj_w0, 0, lane); cp_commit();
    issue_adj_warp(wbuf + 1 * WBUF_FLOATS, adj_w0, 1, lane); cp_commit();
    issue_adj_warp(wbuf + 2 * WBUF_FLOATS, adj_w0, 2, lane); cp_commit();

    // ---- stage node[b] as shared B tile (tf32, pair-interleaved) ----
    {
        const float4* src = (const float4*)(node + (size_t)b * N_SZ * F_SZ);
#pragma unroll
        for (int i = 0; i < 16; ++i) {
            const int q = tid + i * NTHREADS;   // 4096 float4
            const int r = q >> 4;
            const int c = (q & 15) << 2;
            float4 v = src[q];
            sh_node[paddr(r, c + 0)] = __uint_as_float(f2tf(v.x));
            sh_node[paddr(r, c + 1)] = __uint_as_float(f2tf(v.y));
            sh_node[paddr(r, c + 2)] = __uint_as_float(f2tf(v.z));
            sh_node[paddr(r, c + 3)] = __uint_as_float(f2tf(v.w));
        }
    }
    stage_W(sh_w, W_add, tid);                 // W buffer = W_add
    if (tid < 64) sh_ba[tid] = b_add[tid];
    sh_be[tid] = b_edge[tid];                  // all 4 edge biases
    __syncthreads();

    // ---- residual: oacc = b_add + node @ W_add ----
    float oacc[2][8][4];
#pragma unroll
    for (int nt = 0; nt < 8; ++nt) {
        const float v0 = sh_ba[8 * nt + 2 * qc];
        const float v1 = sh_ba[8 * nt + 2 * qc + 1];
#pragma unroll
        for (int j = 0; j < 2; ++j) {
            oacc[j][nt][0] = v0; oacc[j][nt][1] = v1;
            oacc[j][nt][2] = v0; oacc[j][nt][3] = v1;
        }
    }
#pragma unroll
    for (int s = 0; s < 8; ++s) {
        uint32_t bf[8][2];
        const int kr0 = 8 * s + qc;
#pragma unroll
        for (int nt = 0; nt < 8; ++nt) {
            const int cc = (8 * nt + qr) ^ (qc << 3);
            bf[nt][0] = *(const uint32_t*)&sh_w[kr0 * 64 + cc];
            bf[nt][1] = *(const uint32_t*)&sh_w[(kr0 + 4) * 64 + cc];
        }
#pragma unroll
        for (int j = 0; j < 2; ++j) {
            const int r0 = mrow + 16 * j + qr;
            uint32_t af[4];
            af[0] = *(const uint32_t*)&sh_node[paddr(r0,     8 * s + qc)];
            af[1] = *(const uint32_t*)&sh_node[paddr(r0 + 8, 8 * s + qc)];
            af[2] = *(const uint32_t*)&sh_node[paddr(r0,     8 * s + qc + 4)];
            af[3] = *(const uint32_t*)&sh_node[paddr(r0 + 8, 8 * s + qc + 4)];
#pragma unroll
            for (int nt = 0; nt < 8; ++nt) mma_tf32(oacc[j][nt], af, bf[nt]);
        }
    }

    __syncthreads();                           // residual reads of W_add done
    stage_W(sh_w, W_edge, tid);                // W buffer = W_0
    __syncthreads();

    // ---- flat streaming loop: 32 chunks (4 edges x 8), 3 chunks in flight ----
    float pacc[2][8][4];
#pragma unroll
    for (int j = 0; j < 2; ++j)
#pragma unroll
        for (int nt = 0; nt < 8; ++nt)
#pragma unroll
            for (int i = 0; i < 4; ++i) pacc[j][nt][i] = 0.0f;
    float rs[2][2] = {{0.0f, 0.0f}, {0.0f, 0.0f}};

#pragma unroll 1
    for (int g = 0; g < 32; ++g) {
        const int e  = g >> 3;
        const int kc = g & 7;

        __syncwarp();   // all lanes done reading slot (g+3)&3 (consumed at g-1)
        if (g + 3 < 32) {
            const int gn = g + 3;
            issue_adj_warp(wbuf + (gn & 3) * WBUF_FLOATS,
                           adj_b + (((size_t)(gn >> 3)) << 16) + mrow * 256,
                           gn & 7, lane);
            cp_commit();
        }
        if (g <= 28)      cp_wait<3>();
        else if (g == 29) cp_wait<2>();
        else if (g == 30) cp_wait<1>();
        else              cp_wait<0>();
        __syncwarp();   // chunk g visible to all lanes

        const float* abuf = wbuf + (g & 3) * WBUF_FLOATS;
#pragma unroll
        for (int s = 0; s < 4; ++s) {
            const float* gbase = sh_node + ((4 * kc + s) << 9);
            uint32_t bf[8][2];
#pragma unroll
            for (int nt = 0; nt < 8; ++nt) {
                uint2 pr = *(const uint2*)&gbase[((8 * nt + qr) << 3) + (qc << 1)];
                bf[nt][0] = pr.x; bf[nt][1] = pr.y;
            }
            const int cl = 8 * s + qc;
#pragma unroll
            for (int j = 0; j < 2; ++j) {
                const int lr = 16 * j + qr;
                uint32_t af[4];
                af[0] = *(const uint32_t*)&abuf[lr * ADJ_STRIDE + cl];
                af[1] = *(const uint32_t*)&abuf[(lr + 8) * ADJ_STRIDE + cl];
                af[2] = *(const uint32_t*)&abuf[lr * ADJ_STRIDE + cl + 4];
                af[3] = *(const uint32_t*)&abuf[(lr + 8) * ADJ_STRIDE + cl + 4];
                rs[j][0] += __uint_as_float(af[0]) + __uint_as_float(af[2]);
                rs[j][1] += __uint_as_float(af[1]) + __uint_as_float(af[3]);
#pragma unroll
                for (int nt = 0; nt < 8; ++nt) mma_tf32(pacc[j][nt], af, bf[nt]);
            }
        }

        if (kc == 7) {
            // ---- edge boundary: rowsum x b_e, then oacc += P_e @ W_e ----
            const float* be = sh_be + (e << 6);
            float rt[2][2];
#pragma unroll
            for (int j = 0; j < 2; ++j)
#pragma unroll
                for (int i = 0; i < 2; ++i) {
                    float v = rs[j][i];
                    v += __shfl_xor_sync(0xffffffffu, v, 1);
                    v += __shfl_xor_sync(0xffffffffu, v, 2);
                    rt[j][i] = v;
                    rs[j][i] = 0.0f;
                }
#pragma unroll
            for (int nt = 0; nt < 8; ++nt) {
                const float b0 = be[8 * nt + 2 * qc];
                const float b1 = be[8 * nt + 2 * qc + 1];
#pragma unroll
                for (int j = 0; j < 2; ++j) {
                    oacc[j][nt][0] += rt[j][0] * b0;
                    oacc[j][nt][1] += rt[j][0] * b1;
                    oacc[j][nt][2] += rt[j][1] * b0;
                    oacc[j][nt][3] += rt[j][1] * b1;
                }
            }
            // small GEMM: A-frags from pacc via intra-quad shuffles, B = W_e
            const int L1 = (lane & ~3) | (qc >> 1);
            const int L2 = L1 ^ 2;
            const bool odd = qc & 1;
#pragma unroll
            for (int s = 0; s < 8; ++s) {
                uint32_t bf[8][2];
                const int kr0 = 8 * s + qc;
#pragma unroll
                for (int nt = 0; nt < 8; ++nt) {
                    const int cc = (8 * nt + qr) ^ (qc << 3);
                    bf[nt][0] = *(const uint32_t*)&sh_w[kr0 * 64 + cc];
                    bf[nt][1] = *(const uint32_t*)&sh_w[(kr0 + 4) * 64 + cc];
                }
#pragma unroll
                for (int j = 0; j < 2; ++j) {
                    const float v00 = __shfl_sync(0xffffffffu, pacc[j][s][0], L1);
                    const float v01 = __shfl_sync(0xffffffffu, pacc[j][s][1], L1);
                    const float v10 = __shfl_sync(0xffffffffu, pacc[j][s][2], L1);
                    const float v11 = __shfl_sync(0xffffffffu, pacc[j][s][3], L1);
                    const float u00 = __shfl_sync(0xffffffffu, pacc[j][s][0], L2);
                    const float u01 = __shfl_sync(0xffffffffu, pacc[j][s][1], L2);
                    const float u10 = __shfl_sync(0xffffffffu, pacc[j][s][2], L2);
                    const float u11 = __shfl_sync(0xffffffffu, pacc[j][s][3], L2);
                    uint32_t a[4];
                    a[0] = f2tf(odd ? v01 : v00);
                    a[1] = f2tf(odd ? v11 : v10);
                    a[2] = f2tf(odd ? u01 : u00);
                    a[3] = f2tf(odd ? u11 : u10);
#pragma unroll
                    for (int nt = 0; nt < 8; ++nt) mma_tf32(oacc[j][nt], a, bf[nt]);
                }
            }
            // reset P accumulators for next edge
#pragma unroll
            for (int j = 0; j < 2; ++j)
#pragma unroll
                for (int nt = 0; nt < 8; ++nt)
#pragma unroll
                    for (int i = 0; i < 4; ++i) pacc[j][nt][i] = 0.0f;

            if (e < 3) {
                __syncthreads();   // all warps done with W_e
                stage_W(sh_w, W_edge + (e + 1) * 4096, tid);
                __syncthreads();   // W_{e+1} visible (next-edge chunks already in flight)
            }
        }
    }

    // ---- epilogue: write out[b] ----
    float* ob = out + (size_t)b * N_SZ * F_SZ;
#pragma unroll
    for (int j = 0; j < 2; ++j) {
#pragma unroll
        for (int nt = 0; nt < 8; ++nt) {
            const int r0 = mrow + 16 * j + qr;
            const int c0 = 8 * nt + 2 * qc;
            *(float2*)&ob[r0 * 64 + c0]       = make_float2(oacc[j][nt][0], oacc[j][nt][1]);
            *(float2*)&ob[(r0 + 8) * 64 + c0] = make_float2(oacc[j][nt][2], oacc[j][nt][3]);
        }
    }
}

extern "C" void kernel_launch(void* const* d_in, const int* in_sizes, int n_in,
                              void* d_out, int out_size) {
    const float* node   = (const float*)d_in[0];
    const float* adj    = (const float*)d_in[1];
    const float* W_edge = (const float*)d_in[2];
    const float* b_edge = (const float*)d_in[3];
    const float* W_add  = (const float*)d_in[4];
    const float* b_add  = (const float*)d_in[5];
    float* out = (float*)d_out;

    cudaFuncSetAttribute(graphconv_tf32_kernel,
                         cudaFuncAttributeMaxDynamicSharedMemorySize, SMEM_BYTES);
    graphconv_tf32_kernel<<<512, NTHREADS, SMEM_BYTES>>>(node, adj, W_edge, b_edge,
                                                         W_add, b_add, out);
}